// round 15
// baseline (speedup 1.0000x reference)
#include <cuda_runtime.h>
#include <cuda_fp16.h>
#include <cstdint>

#define N_NODES 32768
#define EMBED_DIM 512
#define NNZ 1048576
#define LN_EPS 1e-5f

// ---------------- scratch (device globals; no allocation allowed) ----------------
__device__ __align__(16) __half g_support_h[N_NODES * EMBED_DIM];  // 32 MB fp16 support
__device__ __align__(16) int g_cnt[N_NODES];  // zero-init at load; re-zeroed by scanA each run
__device__ int   g_ptr[N_NODES + 1];
__device__ int   g_offs[N_NODES];
__device__ int   g_bsum[32];
__device__ int   g_sA_done;               // scanA completion counter (reset by scanB)
__device__ int   g_mid_flag;              // scanB->scatter flag (reset by spmm block 0)
__device__ __align__(8) int2 g_edge[NNZ]; // (col, val bits)
__device__ __align__(16) __half g_A_h[N_NODES * EMBED_DIM];        // 32 MB fp16 gathered A
__device__ __align__(16) __half g_Bt_h[EMBED_DIM * EMBED_DIM];     // W^T fp16, [n][k]

__device__ __forceinline__ uint32_t smem_u32(const void* p) {
    uint32_t a;
    asm("{ .reg .u64 t; cvta.to.shared.u64 t, %1; cvt.u32.u64 %0, t; }" : "=r"(a) : "l"(p));
    return a;
}

// ---------------- prep_all: W transpose + edge histogram + embedding gather ----------------
// blocks [0,1024): W transpose; [1024,5120): hist; [5120,13312): gather.
__global__ __launch_bounds__(256) void prep_all(const float* __restrict__ W,
                                                const int* __restrict__ arow,
                                                const int* __restrict__ uid,
                                                const float* __restrict__ emb) {
    int b = blockIdx.x, t = threadIdx.x;
    if (b < 1024) {
        int k = b >> 1;
        int n = ((b & 1) << 8) + t;
        g_Bt_h[(size_t)n * EMBED_DIM + k] = __float2half_rn(W[k * EMBED_DIM + n]);
    } else if (b < 5120) {
        int e = (b - 1024) * 256 + t;
        atomicAdd(&g_cnt[arow[e]], 1);
    } else {
        int row = (b - 5120) * 4 + (t >> 6);
        int c = (t & 63) * 8;
        int u = __ldg(uid + row);
        const float4* src = (const float4*)(emb + (size_t)u * EMBED_DIM + c);
        float4 v0 = src[0];
        float4 v1 = src[1];
        __half2 h0 = __floats2half2_rn(v0.x, v0.y);
        __half2 h1 = __floats2half2_rn(v0.z, v0.w);
        __half2 h2 = __floats2half2_rn(v1.x, v1.y);
        __half2 h3 = __floats2half2_rn(v1.z, v1.w);
        uint4* dst = (uint4*)(g_A_h + (size_t)row * EMBED_DIM + c);
        dst[0] = make_uint4(*(uint32_t*)&h0, *(uint32_t*)&h1, *(uint32_t*)&h2, *(uint32_t*)&h3);
    }
}

// ---------------- fused mid kernel: scanA + scanB + GEMM + scatter ----------------
// blocks [0,32): scanA; [32]: scanB (spin on scanA); [33,1057): gemm; [1057,5153): scatter
// (spin on scanB flag). GEMM depends only on prep (kernel boundary), starts immediately.
#define STAGE_B 16384
#define N_CHUNKS 16
#define GEMM_B0 33
#define SCAT_B0 1057

__device__ __forceinline__ uint32_t sw_off(int row, int un) {
    return (uint32_t)(row * 64 + ((un ^ ((row >> 1) & 3)) << 4));
}

__device__ __forceinline__ void ld_stage(uint32_t st, const char* Ag, const char* Bg, int tid) {
#pragma unroll
    for (int j = 0; j < 2; j++) {
        int u = tid + j * 256;
        int row = u >> 2, un = u & 3;
        uint32_t so = sw_off(row, un);
        size_t go = (size_t)row * 1024 + un * 16;
        asm volatile("cp.async.cg.shared.global [%0], [%1], 16;" :: "r"(st + so), "l"(Ag + go));
        asm volatile("cp.async.cg.shared.global [%0], [%1], 16;" :: "r"(st + 8192 + so), "l"(Bg + go));
    }
}

__global__ __launch_bounds__(256, 2) void mid_fused(const int* __restrict__ arow,
                                                    const int* __restrict__ acol,
                                                    const float* __restrict__ avals) {
    __shared__ __align__(128) char smem[3 * STAGE_B];
    int tid = threadIdx.x;
    int b = blockIdx.x;

    if (b < 32) {
        // ---- scanA: exclusive scan of one 1024-count chunk; zero g_cnt ----
        __shared__ int sh[256];
        int base = b * 1024 + tid * 4;
        int4 v = *(int4*)&g_cnt[base];
        *(int4*)&g_cnt[base] = make_int4(0, 0, 0, 0);
        int s = v.x + v.y + v.z + v.w;
        sh[tid] = s;
        __syncthreads();
        for (int o = 1; o < 256; o <<= 1) {
            int tmp = (tid >= o) ? sh[tid - o] : 0;
            __syncthreads();
            sh[tid] += tmp;
            __syncthreads();
        }
        int run = sh[tid] - s;   // exclusive prefix of this thread's 4
        g_ptr[base] = run; run += v.x;
        g_ptr[base + 1] = run; run += v.y;
        g_ptr[base + 2] = run; run += v.z;
        g_ptr[base + 3] = run;
        if (tid == 255) g_bsum[b] = sh[255];
        __syncthreads();
        if (tid == 0) { __threadfence(); atomicAdd(&g_sA_done, 1); }
        return;
    }

    if (b == 32) {
        // ---- scanB: wait for scanA, add block offsets, publish flag ----
        __shared__ int boff[33];
        if (tid == 0) {
            while (atomicAdd(&g_sA_done, 0) < 32) __nanosleep(128);
            __threadfence();
        }
        __syncthreads();
        if (tid == 0) {
            int run = 0;
#pragma unroll
            for (int i = 0; i < 32; i++) { boff[i] = run; run += g_bsum[i]; }
            boff[32] = run;
            g_sA_done = 0;               // reset for next replay
        }
        __syncthreads();
#pragma unroll
        for (int j = 0; j < 128; j++) {
            int idx = j * 256 + tid;
            int val = g_ptr[idx] + boff[idx >> 10];
            g_ptr[idx] = val;
            g_offs[idx] = val;
        }
        if (tid == 0) g_ptr[N_NODES] = boff[32];
        __syncthreads();
        if (tid == 0) { __threadfence(); atomicExch(&g_mid_flag, 1); }
        return;
    }

    if (b >= SCAT_B0) {
        // ---- scatter: wait for scanB's g_offs ----
        if (tid == 0) {
            while (atomicAdd(&g_mid_flag, 0) == 0) __nanosleep(128);
            __threadfence();
        }
        __syncthreads();
        int e = (b - SCAT_B0) * 256 + tid;
        int r = arow[e];
        int p = atomicAdd(&g_offs[r], 1);
        g_edge[p] = make_int2(acol[e], __float_as_int(avals[e]));
        return;
    }

    // ---- GEMM tile ----
    int bg = b - GEMM_B0;
    int lane = tid & 31, wid = tid >> 5;
    int warp_m = wid & 3, warp_n = wid >> 2;
    int m0 = (bg >> 2) * 128, n0 = (bg & 3) * 128;

    float acc[2][8][4];
#pragma unroll
    for (int mt = 0; mt < 2; mt++)
#pragma unroll
        for (int nt = 0; nt < 8; nt++)
#pragma unroll
            for (int q = 0; q < 4; q++) acc[mt][nt][q] = 0.f;

    const char* Ag = (const char*)g_A_h + (size_t)m0 * 1024;
    const char* Bg = (const char*)g_Bt_h + (size_t)n0 * 1024;

    uint32_t sbase = smem_u32(smem);

    ld_stage(sbase, Ag, Bg, tid);
    asm volatile("cp.async.commit_group;");
    ld_stage(sbase + STAGE_B, Ag + 64, Bg + 64, tid);
    asm volatile("cp.async.commit_group;");

    for (int i = 0; i < N_CHUNKS; i++) {
        if (i < N_CHUNKS - 1) {
            asm volatile("cp.async.wait_group 1;");
        } else {
            asm volatile("cp.async.wait_group 0;");
        }
        __syncthreads();
        if (i + 2 < N_CHUNKS) {
            int koff = (i + 2) * 64;
            ld_stage(sbase + ((i + 2) % 3) * STAGE_B, Ag + koff, Bg + koff, tid);
            asm volatile("cp.async.commit_group;");
        }

        uint32_t aB = sbase + (i % 3) * STAGE_B;
        uint32_t bB = aB + 8192;
#pragma unroll
        for (int kk = 0; kk < 2; kk++) {
            uint32_t bf[8][2];
#pragma unroll
            for (int p = 0; p < 4; p++) {
                int row = warp_n * 64 + p * 16 + (lane >> 4) * 8 + (lane & 7);
                int un = kk * 2 + ((lane >> 3) & 1);
                uint32_t addr = bB + sw_off(row, un);
                asm volatile("ldmatrix.sync.aligned.m8n8.x4.shared.b16 {%0,%1,%2,%3}, [%4];"
                             : "=r"(bf[2 * p][0]), "=r"(bf[2 * p][1]),
                               "=r"(bf[2 * p + 1][0]), "=r"(bf[2 * p + 1][1])
                             : "r"(addr));
            }
            uint32_t a[2][4];
#pragma unroll
            for (int mt = 0; mt < 2; mt++) {
                int row = warp_m * 32 + mt * 16 + ((lane >> 3) & 1) * 8 + (lane & 7);
                int un = kk * 2 + (lane >> 4);
                uint32_t addr = aB + sw_off(row, un);
                asm volatile("ldmatrix.sync.aligned.m8n8.x4.shared.b16 {%0,%1,%2,%3}, [%4];"
                             : "=r"(a[mt][0]), "=r"(a[mt][1]), "=r"(a[mt][2]), "=r"(a[mt][3])
                             : "r"(addr));
            }
#pragma unroll
            for (int mt = 0; mt < 2; mt++)
#pragma unroll
                for (int nt = 0; nt < 8; nt++) {
                    asm volatile(
                        "mma.sync.aligned.m16n8k16.row.col.f32.f16.f16.f32 "
                        "{%0,%1,%2,%3}, {%4,%5,%6,%7}, {%8,%9}, {%0,%1,%2,%3};"
                        : "+f"(acc[mt][nt][0]), "+f"(acc[mt][nt][1]),
                          "+f"(acc[mt][nt][2]), "+f"(acc[mt][nt][3])
                        : "r"(a[mt][0]), "r"(a[mt][1]), "r"(a[mt][2]), "r"(a[mt][3]),
                          "r"(bf[nt][0]), "r"(bf[nt][1]));
                }
        }
    }

    // epilogue: fp16 support store
    int g = lane >> 2, tg = lane & 3;
#pragma unroll
    for (int mt = 0; mt < 2; mt++) {
        int m = m0 + warp_m * 32 + mt * 16 + g;
#pragma unroll
        for (int nt = 0; nt < 8; nt++) {
            int n = n0 + warp_n * 64 + nt * 8 + tg * 2;
            __half2 lo2 = __floats2half2_rn(acc[mt][nt][0], acc[mt][nt][1]);
            __half2 hi2 = __floats2half2_rn(acc[mt][nt][2], acc[mt][nt][3]);
            *(__half2*)(g_support_h + (size_t)m * EMBED_DIM + n) = lo2;
            *(__half2*)(g_support_h + (size_t)(m + 8) * EMBED_DIM + n) = hi2;
        }
    }
}

// ---------------- fused SpMM (CSR, fp16 support, double-buffered staging) + bias + LN ----
__global__ __launch_bounds__(64) void spmm_ln_kernel(const float* __restrict__ bias,
                                                     const float* __restrict__ gamma,
                                                     const float* __restrict__ beta,
                                                     float* __restrict__ out) {
    int r = blockIdx.x;
    int t = threadIdx.x;
    __shared__ int2 s_edge[2][64];
    __shared__ float red[4];

    if (r == 0 && t == 0) g_mid_flag = 0;   // reset for next graph replay

    int beg = g_ptr[r];
    int end = g_ptr[r + 1];

    float acc[8];
#pragma unroll
    for (int q = 0; q < 8; q++) acc[q] = 0.f;

    int p = 0;
    for (int base = beg; base < end; base += 64, p ^= 1) {
        int cnt = min(64, end - base);
        if (t < cnt) s_edge[p][t] = g_edge[base + t];
        __syncthreads();
#pragma unroll 4
        for (int i = 0; i < cnt; i++) {
            int2 e = s_edge[p][i];
            float v = __int_as_float(e.y);
            uint4 raw = *(const uint4*)(g_support_h + (size_t)e.x * EMBED_DIM + t * 8);
            float2 f0 = __half22float2(*reinterpret_cast<__half2*>(&raw.x));
            float2 f1 = __half22float2(*reinterpret_cast<__half2*>(&raw.y));
            float2 f2 = __half22float2(*reinterpret_cast<__half2*>(&raw.z));
            float2 f3 = __half22float2(*reinterpret_cast<__half2*>(&raw.w));
            acc[0] += v * f0.x; acc[1] += v * f0.y;
            acc[2] += v * f1.x; acc[3] += v * f1.y;
            acc[4] += v * f2.x; acc[5] += v * f2.y;
            acc[6] += v * f3.x; acc[7] += v * f3.y;
        }
    }

    const float4* b4 = (const float4*)(bias + t * 8);
    float4 ba = b4[0], bb = b4[1];
    acc[0] += ba.x; acc[1] += ba.y; acc[2] += ba.z; acc[3] += ba.w;
    acc[4] += bb.x; acc[5] += bb.y; acc[6] += bb.z; acc[7] += bb.w;

    float s = 0.f, q = 0.f;
#pragma unroll
    for (int j = 0; j < 8; j++) { s += acc[j]; q += acc[j] * acc[j]; }
#pragma unroll
    for (int o = 16; o > 0; o >>= 1) {
        s += __shfl_down_sync(0xFFFFFFFFu, s, o);
        q += __shfl_down_sync(0xFFFFFFFFu, q, o);
    }
    int lane = t & 31, w = t >> 5;
    if (lane == 0) { red[w] = s; red[2 + w] = q; }
    __syncthreads();
    if (t == 0) {
        float S = red[0] + red[1];
        float Q = red[2] + red[3];
        float mu = S * (1.0f / EMBED_DIM);
        float var = Q * (1.0f / EMBED_DIM) - mu * mu;
        red[0] = mu;
        red[1] = rsqrtf(var + LN_EPS);
    }
    __syncthreads();
    float mu = red[0], rs = red[1];

    const float4* g4 = (const float4*)(gamma + t * 8);
    const float4* be4 = (const float4*)(beta + t * 8);
    float4 g0 = g4[0], g1 = g4[1], e0 = be4[0], e1 = be4[1];
    float4 o0, o1;
    o0.x = (acc[0] - mu) * rs * g0.x + e0.x;
    o0.y = (acc[1] - mu) * rs * g0.y + e0.y;
    o0.z = (acc[2] - mu) * rs * g0.z + e0.z;
    o0.w = (acc[3] - mu) * rs * g0.w + e0.w;
    o1.x = (acc[4] - mu) * rs * g1.x + e1.x;
    o1.y = (acc[5] - mu) * rs * g1.y + e1.y;
    o1.z = (acc[6] - mu) * rs * g1.z + e1.z;
    o1.w = (acc[7] - mu) * rs * g1.w + e1.w;
    float4* op = (float4*)(out + (size_t)r * EMBED_DIM + t * 8);
    op[0] = o0;
    op[1] = o1;
}

// ---------------- launch ----------------
extern "C" void kernel_launch(void* const* d_in, const int* in_sizes, int n_in,
                              void* d_out, int out_size) {
    const int*   uid   = (const int*)d_in[0];
    const int*   arow  = (const int*)d_in[1];
    const int*   acol  = (const int*)d_in[2];
    const float* avals = (const float*)d_in[3];
    const float* emb   = (const float*)d_in[4];
    const float* W     = (const float*)d_in[5];
    const float* bias  = (const float*)d_in[6];
    const float* gamma = (const float*)d_in[7];
    const float* beta  = (const float*)d_in[8];
    float* out = (float*)d_out;

    prep_all<<<13312, 256>>>(W, arow, uid, emb);
    mid_fused<<<5153, 256>>>(arow, acol, avals);
    spmm_ln_kernel<<<N_NODES, 64>>>(bias, gamma, beta, out);
}

// round 16
// speedup vs baseline: 1.0404x; 1.0404x over previous
#include <cuda_runtime.h>
#include <cuda_fp16.h>
#include <cstdint>

#define N_NODES 32768
#define EMBED_DIM 512
#define NNZ 1048576
#define LN_EPS 1e-5f

// ---------------- scratch (device globals; no allocation allowed) ----------------
__device__ __align__(16) __half g_support_h[N_NODES * EMBED_DIM];  // 32 MB fp16 support
__device__ int   g_cnt[N_NODES];          // zero-init at load; re-zeroed by scan each run
__device__ int   g_ptr[N_NODES + 1];
__device__ int   g_offs[N_NODES];
__device__ int   g_bsum[32];
__device__ int   g_scan_cnt;              // last-block-done counter (reset in-kernel)
__device__ __align__(8) int2 g_edge[NNZ]; // (col, val bits)
__device__ __align__(16) __half g_A_h[N_NODES * EMBED_DIM];        // 32 MB fp16 gathered A
__device__ __align__(16) __half g_Bt_h[EMBED_DIM * EMBED_DIM];     // W^T fp16, [n][k]

__device__ __forceinline__ uint32_t smem_u32(const void* p) {
    uint32_t a;
    asm("{ .reg .u64 t; cvta.to.shared.u64 t, %1; cvt.u32.u64 %0, t; }" : "=r"(a) : "l"(p));
    return a;
}

// ---------------- prep_all: W transpose + edge histogram + embedding gather ----------------
// blocks [0,1024): W transpose; [1024,5120): hist; [5120,13312): gather.
__global__ __launch_bounds__(256) void prep_all(const float* __restrict__ W,
                                                const int* __restrict__ arow,
                                                const int* __restrict__ uid,
                                                const float* __restrict__ emb) {
    int b = blockIdx.x, t = threadIdx.x;
    if (b < 1024) {
        int k = b >> 1;
        int n = ((b & 1) << 8) + t;
        g_Bt_h[(size_t)n * EMBED_DIM + k] = __float2half_rn(W[k * EMBED_DIM + n]);
    } else if (b < 5120) {
        int e = (b - 1024) * 256 + t;
        atomicAdd(&g_cnt[arow[e]], 1);
    } else {
        int row = (b - 5120) * 4 + (t >> 6);
        int c = (t & 63) * 8;
        int u = __ldg(uid + row);
        const float4* src = (const float4*)(emb + (size_t)u * EMBED_DIM + c);
        float4 v0 = src[0];
        float4 v1 = src[1];
        __half2 h0 = __floats2half2_rn(v0.x, v0.y);
        __half2 h1 = __floats2half2_rn(v0.z, v0.w);
        __half2 h2 = __floats2half2_rn(v1.x, v1.y);
        __half2 h3 = __floats2half2_rn(v1.z, v1.w);
        uint4* dst = (uint4*)(g_A_h + (size_t)row * EMBED_DIM + c);
        dst[0] = make_uint4(*(uint32_t*)&h0, *(uint32_t*)&h1, *(uint32_t*)&h2, *(uint32_t*)&h3);
    }
}

// ---------------- fused scan: per-chunk scan + last-block adds offsets ----------------
__global__ __launch_bounds__(1024) void scan_fused() {
    __shared__ int sh[1024];
    __shared__ int boff[33];
    __shared__ int is_last;
    int b = blockIdx.x, t = threadIdx.x;
    int idx = b * 1024 + t;
    int v = g_cnt[idx];
    g_cnt[idx] = 0;                      // reset for next graph replay
    sh[t] = v;
    __syncthreads();
    for (int o = 1; o < 1024; o <<= 1) {
        int tmp = (t >= o) ? sh[t - o] : 0;
        __syncthreads();
        sh[t] += tmp;
        __syncthreads();
    }
    g_ptr[idx] = sh[t] - v;              // local exclusive prefix
    if (t == 1023) g_bsum[b] = sh[t];
    // last-block-done: the 32nd block to finish performs phase B
    __threadfence();
    __syncthreads();
    if (t == 0) {
        int c = atomicAdd(&g_scan_cnt, 1);
        is_last = (c == 31);
        if (c == 31) g_scan_cnt = 0;     // reset for next replay
    }
    __syncthreads();
    if (!is_last) return;
    __threadfence();                     // acquire all blocks' g_ptr/g_bsum writes
    if (t == 0) {
        int run = 0;
#pragma unroll
        for (int i = 0; i < 32; i++) { boff[i] = run; run += g_bsum[i]; }
        boff[32] = run;
    }
    __syncthreads();
#pragma unroll
    for (int j = 0; j < 32; j++) {
        int k = j * 1024 + t;
        int val = g_ptr[k] + boff[j];
        g_ptr[k] = val;
        g_offs[k] = val;
    }
    if (t == 0) g_ptr[N_NODES] = boff[32];
}

// ---------------- GEMM (single-pass fp16, BK=32, 3-stage, 1 barrier/iter) + scatter ------
#define STAGE_B 16384
#define N_CHUNKS 16

__device__ __forceinline__ uint32_t sw_off(int row, int un) {
    return (uint32_t)(row * 64 + ((un ^ ((row >> 1) & 3)) << 4));
}

__device__ __forceinline__ void ld_stage(uint32_t st, const char* Ag, const char* Bg, int tid) {
#pragma unroll
    for (int j = 0; j < 2; j++) {
        int u = tid + j * 256;
        int row = u >> 2, un = u & 3;
        uint32_t so = sw_off(row, un);
        size_t go = (size_t)row * 1024 + un * 16;
        asm volatile("cp.async.cg.shared.global [%0], [%1], 16;" :: "r"(st + so), "l"(Ag + go));
        asm volatile("cp.async.cg.shared.global [%0], [%1], 16;" :: "r"(st + 8192 + so), "l"(Bg + go));
    }
}

__global__ __launch_bounds__(256, 2) void gemm_scatter(const int* __restrict__ arow,
                                                       const int* __restrict__ acol,
                                                       const float* __restrict__ avals) {
    __shared__ __align__(128) char smem[3 * STAGE_B];
    int tid = threadIdx.x;

    if (blockIdx.x >= 1024) {
        int e = (blockIdx.x - 1024) * 256 + tid;
        int r = arow[e];
        int p = atomicAdd(&g_offs[r], 1);
        g_edge[p] = make_int2(acol[e], __float_as_int(avals[e]));
        return;
    }

    int lane = tid & 31, wid = tid >> 5;
    int warp_m = wid & 3, warp_n = wid >> 2;
    int m0 = (blockIdx.x >> 2) * 128, n0 = (blockIdx.x & 3) * 128;

    float acc[2][8][4];
#pragma unroll
    for (int mt = 0; mt < 2; mt++)
#pragma unroll
        for (int nt = 0; nt < 8; nt++)
#pragma unroll
            for (int q = 0; q < 4; q++) acc[mt][nt][q] = 0.f;

    const char* Ag = (const char*)g_A_h + (size_t)m0 * 1024;
    const char* Bg = (const char*)g_Bt_h + (size_t)n0 * 1024;

    uint32_t sbase = smem_u32(smem);

    ld_stage(sbase, Ag, Bg, tid);
    asm volatile("cp.async.commit_group;");
    ld_stage(sbase + STAGE_B, Ag + 64, Bg + 64, tid);
    asm volatile("cp.async.commit_group;");

    for (int i = 0; i < N_CHUNKS; i++) {
        if (i < N_CHUNKS - 1) {
            asm volatile("cp.async.wait_group 1;");
        } else {
            asm volatile("cp.async.wait_group 0;");
        }
        // Single barrier per iteration: also orders compute on stage i-1 before
        // ld_stage overwrites stage (i+2)%3 == (i-1)%3.
        __syncthreads();
        if (i + 2 < N_CHUNKS) {
            int koff = (i + 2) * 64;
            ld_stage(sbase + ((i + 2) % 3) * STAGE_B, Ag + koff, Bg + koff, tid);
            asm volatile("cp.async.commit_group;");
        }

        uint32_t aB = sbase + (i % 3) * STAGE_B;
        uint32_t bB = aB + 8192;
#pragma unroll
        for (int kk = 0; kk < 2; kk++) {
            uint32_t b[8][2];
#pragma unroll
            for (int p = 0; p < 4; p++) {
                int row = warp_n * 64 + p * 16 + (lane >> 4) * 8 + (lane & 7);
                int un = kk * 2 + ((lane >> 3) & 1);
                uint32_t addr = bB + sw_off(row, un);
                asm volatile("ldmatrix.sync.aligned.m8n8.x4.shared.b16 {%0,%1,%2,%3}, [%4];"
                             : "=r"(b[2 * p][0]), "=r"(b[2 * p][1]),
                               "=r"(b[2 * p + 1][0]), "=r"(b[2 * p + 1][1])
                             : "r"(addr));
            }
            uint32_t a[2][4];
#pragma unroll
            for (int mt = 0; mt < 2; mt++) {
                int row = warp_m * 32 + mt * 16 + ((lane >> 3) & 1) * 8 + (lane & 7);
                int un = kk * 2 + (lane >> 4);
                uint32_t addr = aB + sw_off(row, un);
                asm volatile("ldmatrix.sync.aligned.m8n8.x4.shared.b16 {%0,%1,%2,%3}, [%4];"
                             : "=r"(a[mt][0]), "=r"(a[mt][1]), "=r"(a[mt][2]), "=r"(a[mt][3])
                             : "r"(addr));
            }
#pragma unroll
            for (int mt = 0; mt < 2; mt++)
#pragma unroll
                for (int nt = 0; nt < 8; nt++) {
                    asm volatile(
                        "mma.sync.aligned.m16n8k16.row.col.f32.f16.f16.f32 "
                        "{%0,%1,%2,%3}, {%4,%5,%6,%7}, {%8,%9}, {%0,%1,%2,%3};"
                        : "+f"(acc[mt][nt][0]), "+f"(acc[mt][nt][1]),
                          "+f"(acc[mt][nt][2]), "+f"(acc[mt][nt][3])
                        : "r"(a[mt][0]), "r"(a[mt][1]), "r"(a[mt][2]), "r"(a[mt][3]),
                          "r"(b[nt][0]), "r"(b[nt][1]));
                }
        }
    }

    // epilogue: fp16 support store
    int g = lane >> 2, tg = lane & 3;
#pragma unroll
    for (int mt = 0; mt < 2; mt++) {
        int m = m0 + warp_m * 32 + mt * 16 + g;
#pragma unroll
        for (int nt = 0; nt < 8; nt++) {
            int n = n0 + warp_n * 64 + nt * 8 + tg * 2;
            __half2 lo2 = __floats2half2_rn(acc[mt][nt][0], acc[mt][nt][1]);
            __half2 hi2 = __floats2half2_rn(acc[mt][nt][2], acc[mt][nt][3]);
            *(__half2*)(g_support_h + (size_t)m * EMBED_DIM + n) = lo2;
            *(__half2*)(g_support_h + (size_t)(m + 8) * EMBED_DIM + n) = hi2;
        }
    }
}

// ---------------- fused SpMM (CSR, fp16 support, double-buffered staging) + bias + LN ----
__global__ __launch_bounds__(64) void spmm_ln_kernel(const float* __restrict__ bias,
                                                     const float* __restrict__ gamma,
                                                     const float* __restrict__ beta,
                                                     float* __restrict__ out) {
    int r = blockIdx.x;
    int t = threadIdx.x;
    __shared__ int2 s_edge[2][64];
    __shared__ float red[4];

    int beg = g_ptr[r];
    int end = g_ptr[r + 1];

    float acc[8];
#pragma unroll
    for (int q = 0; q < 8; q++) acc[q] = 0.f;

    int p = 0;
    for (int base = beg; base < end; base += 64, p ^= 1) {
        int cnt = min(64, end - base);
        if (t < cnt) s_edge[p][t] = g_edge[base + t];
        __syncthreads();
#pragma unroll 4
        for (int i = 0; i < cnt; i++) {
            int2 e = s_edge[p][i];
            float v = __int_as_float(e.y);
            uint4 raw = *(const uint4*)(g_support_h + (size_t)e.x * EMBED_DIM + t * 8);
            float2 f0 = __half22float2(*reinterpret_cast<__half2*>(&raw.x));
            float2 f1 = __half22float2(*reinterpret_cast<__half2*>(&raw.y));
            float2 f2 = __half22float2(*reinterpret_cast<__half2*>(&raw.z));
            float2 f3 = __half22float2(*reinterpret_cast<__half2*>(&raw.w));
            acc[0] += v * f0.x; acc[1] += v * f0.y;
            acc[2] += v * f1.x; acc[3] += v * f1.y;
            acc[4] += v * f2.x; acc[5] += v * f2.y;
            acc[6] += v * f3.x; acc[7] += v * f3.y;
        }
    }

    const float4* b4 = (const float4*)(bias + t * 8);
    float4 ba = b4[0], bb = b4[1];
    acc[0] += ba.x; acc[1] += ba.y; acc[2] += ba.z; acc[3] += ba.w;
    acc[4] += bb.x; acc[5] += bb.y; acc[6] += bb.z; acc[7] += bb.w;

    float s = 0.f, q = 0.f;
#pragma unroll
    for (int j = 0; j < 8; j++) { s += acc[j]; q += acc[j] * acc[j]; }
#pragma unroll
    for (int o = 16; o > 0; o >>= 1) {
        s += __shfl_down_sync(0xFFFFFFFFu, s, o);
        q += __shfl_down_sync(0xFFFFFFFFu, q, o);
    }
    int lane = t & 31, w = t >> 5;
    if (lane == 0) { red[w] = s; red[2 + w] = q; }
    __syncthreads();
    if (t == 0) {
        float S = red[0] + red[1];
        float Q = red[2] + red[3];
        float mu = S * (1.0f / EMBED_DIM);
        float var = Q * (1.0f / EMBED_DIM) - mu * mu;
        red[0] = mu;
        red[1] = rsqrtf(var + LN_EPS);
    }
    __syncthreads();
    float mu = red[0], rs = red[1];

    const float4* g4 = (const float4*)(gamma + t * 8);
    const float4* be4 = (const float4*)(beta + t * 8);
    float4 g0 = g4[0], g1 = g4[1], e0 = be4[0], e1 = be4[1];
    float4 o0, o1;
    o0.x = (acc[0] - mu) * rs * g0.x + e0.x;
    o0.y = (acc[1] - mu) * rs * g0.y + e0.y;
    o0.z = (acc[2] - mu) * rs * g0.z + e0.z;
    o0.w = (acc[3] - mu) * rs * g0.w + e0.w;
    o1.x = (acc[4] - mu) * rs * g1.x + e1.x;
    o1.y = (acc[5] - mu) * rs * g1.y + e1.y;
    o1.z = (acc[6] - mu) * rs * g1.z + e1.z;
    o1.w = (acc[7] - mu) * rs * g1.w + e1.w;
    float4* op = (float4*)(out + (size_t)r * EMBED_DIM + t * 8);
    op[0] = o0;
    op[1] = o1;
}

// ---------------- launch ----------------
extern "C" void kernel_launch(void* const* d_in, const int* in_sizes, int n_in,
                              void* d_out, int out_size) {
    const int*   uid   = (const int*)d_in[0];
    const int*   arow  = (const int*)d_in[1];
    const int*   acol  = (const int*)d_in[2];
    const float* avals = (const float*)d_in[3];
    const float* emb   = (const float*)d_in[4];
    const float* W     = (const float*)d_in[5];
    const float* bias  = (const float*)d_in[6];
    const float* gamma = (const float*)d_in[7];
    const float* beta  = (const float*)d_in[8];
    float* out = (float*)d_out;

    prep_all<<<13312, 256>>>(W, arow, uid, emb);
    scan_fused<<<32, 1024>>>();
    gemm_scatter<<<5120, 256>>>(arow, acol, avals);
    spmm_ln_kernel<<<N_NODES, 64>>>(bias, gamma, beta, out);
}